// round 5
// baseline (speedup 1.0000x reference)
#include <cuda_runtime.h>
#include <cuda_bf16.h>
#include <mma.h>
#include <stdint.h>

using namespace nvcuda;

// Problem constants (fixed by the dataset)
#define FIN   256
#define FQK   256
#define NQK   (2 * FQK)          // 512
#define MAXN  20000
#define MROWS 20096              // 157 * 128, padded for unguarded stores
#define SCALING 0.0625f          // FQK^-0.5

// Scratch (no allocation allowed in kernel_launch)
__device__ float g_qk[(size_t)MROWS * NQK];
__device__ __nv_bfloat16 g_xhi[(size_t)MROWS * FIN];
__device__ __nv_bfloat16 g_xlo[(size_t)MROWS * FIN];
__device__ __nv_bfloat16 g_whi[(size_t)NQK * FIN];
__device__ __nv_bfloat16 g_wlo[(size_t)NQK * FIN];

// ===========================================================================
// Kernel 0: split fp32 -> bf16 hi + bf16 lo (3-term Kahan-style split).
// One thread per float4.
// ===========================================================================
__global__ __launch_bounds__(256)
void split_kernel(const float* __restrict__ src,
                  __nv_bfloat16* __restrict__ hi,
                  __nv_bfloat16* __restrict__ lo,
                  int n4)
{
    const int i = blockIdx.x * blockDim.x + threadIdx.x;
    if (i >= n4) return;
    float4 v = ((const float4*)src)[i];
    __nv_bfloat16 hx = __float2bfloat16(v.x);
    __nv_bfloat16 hy = __float2bfloat16(v.y);
    __nv_bfloat16 hz = __float2bfloat16(v.z);
    __nv_bfloat16 hw = __float2bfloat16(v.w);
    __nv_bfloat162 h01 = __halves2bfloat162(hx, hy);
    __nv_bfloat162 h23 = __halves2bfloat162(hz, hw);
    __nv_bfloat162 l01 = __halves2bfloat162(
        __float2bfloat16(v.x - __bfloat162float(hx)),
        __float2bfloat16(v.y - __bfloat162float(hy)));
    __nv_bfloat162 l23 = __halves2bfloat162(
        __float2bfloat16(v.z - __bfloat162float(hz)),
        __float2bfloat16(v.w - __bfloat162float(hw)));
    ((__nv_bfloat162*)hi)[2 * i]     = h01;
    ((__nv_bfloat162*)hi)[2 * i + 1] = h23;
    ((__nv_bfloat162*)lo)[2 * i]     = l01;
    ((__nv_bfloat162*)lo)[2 * i + 1] = l23;
}

// ===========================================================================
// Kernel 1: qk = x @ W^T via WMMA bf16x3 on pre-split bf16 inputs.
// CTA tile 128(m) x 128(n), K chunked by 64. 8 warps as 4x2;
// warp tile 32(m) x 64(n) = 2x4 fragments.
// ===========================================================================
#define BM 128
#define BN 128
#define KC 64
#define LDS_ 72                  // padded smem leading dim (bf16 elements)

// smem (bf16 elements): A_hi, A_lo: BM*LDS_ each; B_hi, B_lo: BN*LDS_ each
#define SA_HI 0
#define SA_LO (SA_HI + BM * LDS_)
#define SB_HI (SA_LO + BM * LDS_)
#define SB_LO (SB_HI + BN * LDS_)
#define SM_ELEMS (SB_LO + BN * LDS_)          // 4*128*72 = 36864 bf16 = 73728B

__global__ __launch_bounds__(256)
void gemm_qk_wmma(const __nv_bfloat16* __restrict__ xhi,
                  const __nv_bfloat16* __restrict__ xlo,
                  const __nv_bfloat16* __restrict__ whi,
                  const __nv_bfloat16* __restrict__ wlo,
                  float* __restrict__ qk)
{
    extern __shared__ __nv_bfloat16 sm[];
    const int tid = threadIdx.x;
    const int wid = tid >> 5;
    const int warp_m = wid >> 1;           // 0..3
    const int warp_n = wid & 1;            // 0..1
    const int m0 = blockIdx.y * BM;
    const int n0 = blockIdx.x * BN;
    const float scale = (n0 < FQK) ? SCALING : 1.0f;

    wmma::fragment<wmma::accumulator, 16, 16, 16, float> acc[2][4];
#pragma unroll
    for (int mi = 0; mi < 2; ++mi)
#pragma unroll
        for (int nf = 0; nf < 4; ++nf) wmma::fill_fragment(acc[mi][nf], 0.0f);

    for (int kc = 0; kc < FIN; kc += KC) {
        // ---- copy A tile (128 x 64 bf16, hi+lo): 1024 uint4 each ----
#pragma unroll
        for (int i = 0; i < 4; ++i) {
            const int idx = tid + i * 256;          // 0..1023
            const int r = idx >> 3;                 // row 0..127
            const int c = (idx & 7) * 8;            // bf16 col 0..56
            const size_t goff = (size_t)(m0 + r) * FIN + kc + c;
            *(uint4*)(sm + SA_HI + r * LDS_ + c) = *(const uint4*)(xhi + goff);
            *(uint4*)(sm + SA_LO + r * LDS_ + c) = *(const uint4*)(xlo + goff);
        }
        // ---- copy B tile (128 W-rows x 64 bf16, hi+lo) ----
#pragma unroll
        for (int i = 0; i < 4; ++i) {
            const int idx = tid + i * 256;
            const int r = idx >> 3;
            const int c = (idx & 7) * 8;
            const size_t goff = (size_t)(n0 + r) * FIN + kc + c;
            *(uint4*)(sm + SB_HI + r * LDS_ + c) = *(const uint4*)(whi + goff);
            *(uint4*)(sm + SB_LO + r * LDS_ + c) = *(const uint4*)(wlo + goff);
        }
        __syncthreads();

#pragma unroll
        for (int ks = 0; ks < KC / 16; ++ks) {
            wmma::fragment<wmma::matrix_a, 16, 16, 16, __nv_bfloat16, wmma::row_major> ah[2], al[2];
#pragma unroll
            for (int mi = 0; mi < 2; ++mi) {
                const int row = warp_m * 32 + mi * 16;
                wmma::load_matrix_sync(ah[mi], sm + SA_HI + row * LDS_ + ks * 16, LDS_);
                wmma::load_matrix_sync(al[mi], sm + SA_LO + row * LDS_ + ks * 16, LDS_);
            }
#pragma unroll
            for (int nf = 0; nf < 4; ++nf) {
                const int col = warp_n * 64 + nf * 16;
                wmma::fragment<wmma::matrix_b, 16, 16, 16, __nv_bfloat16, wmma::col_major> bh, bl;
                wmma::load_matrix_sync(bh, sm + SB_HI + col * LDS_ + ks * 16, LDS_);
                wmma::load_matrix_sync(bl, sm + SB_LO + col * LDS_ + ks * 16, LDS_);
#pragma unroll
                for (int mi = 0; mi < 2; ++mi) {
                    wmma::mma_sync(acc[mi][nf], ah[mi], bh, acc[mi][nf]);
                    wmma::mma_sync(acc[mi][nf], ah[mi], bl, acc[mi][nf]);
                    wmma::mma_sync(acc[mi][nf], al[mi], bh, acc[mi][nf]);
                }
            }
        }
        __syncthreads();
    }

    // ---- epilogue: scale + store (qk padded to MROWS, unguarded) ----
#pragma unroll
    for (int mi = 0; mi < 2; ++mi) {
        const int row = m0 + warp_m * 32 + mi * 16;
#pragma unroll
        for (int nf = 0; nf < 4; ++nf) {
#pragma unroll
            for (int t = 0; t < acc[mi][nf].num_elements; ++t)
                acc[mi][nf].x[t] *= scale;
            float* dst = qk + (size_t)row * NQK + n0 + warp_n * 64 + nf * 16;
            wmma::store_matrix_sync(dst, acc[mi][nf], NQK, wmma::mem_row_major);
        }
    }
}

// ===========================================================================
// Kernel 2: fused edge pass. One warp per src node; half-warp per edge,
// 2 edges per iteration. exp values staged in smem; coalesced final write.
// ===========================================================================
#define SMEM_DEG 1024

__device__ __forceinline__ int lower_bound_i(const int* __restrict__ a,
                                             int n, int v)
{
    int lo = 0, hi = n;
    while (lo < hi) {
        int mid = (lo + hi) >> 1;
        if (a[mid] < v) lo = mid + 1; else hi = mid;
    }
    return lo;
}

__global__ __launch_bounds__(256)
void edge_fused_kernel(const int* __restrict__ ei,
                       const float* __restrict__ qk,
                       float* __restrict__ out,
                       int E, int N)
{
    __shared__ float exbuf[8][SMEM_DEG];

    const int wslot = threadIdx.x >> 5;
    const int node  = (blockIdx.x * blockDim.x + threadIdx.x) >> 5;
    const int lane  = threadIdx.x & 31;
    const int t     = lane & 15;          // k-chunk owner within half-warp
    const int s     = lane >> 4;          // edge slot (0 or 1)
    if (node >= N) return;

    const int lo = lower_bound_i(ei, E, node);
    const int hi = lower_bound_i(ei, E, node + 1);
    const int deg = hi - lo;
    if (deg <= 0) return;

    // q chunk: floats [16t, 16t+16)
    const float4* qp = (const float4*)(qk + (size_t)node * NQK);
    float4 qr[4];
#pragma unroll
    for (int i = 0; i < 4; ++i) qr[i] = qp[4 * t + i];

    const int* __restrict__ dest = ei + E;
    const int nIter = (deg + 1) >> 1;
    float sum = 0.0f;

    if (deg <= SMEM_DEG) {
        for (int it = 0; it < nIter; ++it) {
            const int j = lo + 2 * it + s;
            const int jj = (j < hi) ? j : (hi - 1);
            const int d = dest[jj];
            const float4* kp = (const float4*)(qk + (size_t)d * NQK + FQK);
            float4 kv[4];
#pragma unroll
            for (int i = 0; i < 4; ++i) kv[i] = kp[4 * t + i];

            float p = 0.0f;
#pragma unroll
            for (int i = 0; i < 4; ++i) {
                p += qr[i].x * kv[i].x + qr[i].y * kv[i].y
                   + qr[i].z * kv[i].z + qr[i].w * kv[i].w;
            }
            // reduce over 16 lanes (offsets stay within half-warp)
#pragma unroll
            for (int o = 1; o < 16; o <<= 1)
                p += __shfl_xor_sync(0xffffffffu, p, o);

            float ex = __expf(p);
            if (j < hi) {
                sum += ex;
                if (t == 0) exbuf[wslot][j - lo] = ex;
            }
        }
        // combine the two half-warp sums
        sum += __shfl_xor_sync(0xffffffffu, sum, 16);
        const float inv = 1.0f / sum;
        __syncwarp();
        for (int i = lane; i < deg; i += 32)
            out[lo + i] = exbuf[wslot][i] * inv;
    } else {
        // fallback (never taken at these shapes): stage in gmem
        for (int it = 0; it < nIter; ++it) {
            const int j = lo + 2 * it + s;
            const int jj = (j < hi) ? j : (hi - 1);
            const int d = dest[jj];
            const float4* kp = (const float4*)(qk + (size_t)d * NQK + FQK);
            float4 kv[4];
#pragma unroll
            for (int i = 0; i < 4; ++i) kv[i] = kp[4 * t + i];
            float p = 0.0f;
#pragma unroll
            for (int i = 0; i < 4; ++i) {
                p += qr[i].x * kv[i].x + qr[i].y * kv[i].y
                   + qr[i].z * kv[i].z + qr[i].w * kv[i].w;
            }
#pragma unroll
            for (int o = 1; o < 16; o <<= 1)
                p += __shfl_xor_sync(0xffffffffu, p, o);
            float ex = __expf(p);
            if (j < hi) {
                sum += ex;
                if (t == 0) out[j] = ex;
            }
        }
        sum += __shfl_xor_sync(0xffffffffu, sum, 16);
        const float inv = 1.0f / sum;
        __threadfence_block();
        __syncwarp();
        for (int i = lane; i < deg; i += 32)
            out[lo + i] *= inv;
    }
}

// ===========================================================================
extern "C" void kernel_launch(void* const* d_in, const int* in_sizes, int n_in,
                              void* d_out, int out_size)
{
    const float* x   = (const float*)d_in[0];
    const int*   ei  = (const int*)d_in[1];
    const float* W   = (const float*)d_in[2];
    float*       out = (float*)d_out;

    const int N = in_sizes[0] / FIN;     // 20000
    const int E = in_sizes[1] / 2;       // 640000

    float* qk;          cudaGetSymbolAddress((void**)&qk,  g_qk);
    __nv_bfloat16* xhi; cudaGetSymbolAddress((void**)&xhi, g_xhi);
    __nv_bfloat16* xlo; cudaGetSymbolAddress((void**)&xlo, g_xlo);
    __nv_bfloat16* whi; cudaGetSymbolAddress((void**)&whi, g_whi);
    __nv_bfloat16* wlo; cudaGetSymbolAddress((void**)&wlo, g_wlo);

    // 0) split fp32 -> bf16 hi/lo (x and W)
    {
        int n4x = N * FIN / 4;              // 1,280,000
        split_kernel<<<(n4x + 255) / 256, 256>>>(x, xhi, xlo, n4x);
        int n4w = NQK * FIN / 4;            // 32,768
        split_kernel<<<(n4w + 255) / 256, 256>>>(W, whi, wlo, n4w);
    }
    // 1) projection GEMM (bf16x3 WMMA)
    {
        cudaFuncSetAttribute(gemm_qk_wmma,
                             cudaFuncAttributeMaxDynamicSharedMemorySize,
                             SM_ELEMS * (int)sizeof(__nv_bfloat16));
        dim3 grid(NQK / BN, MROWS / BM);
        gemm_qk_wmma<<<grid, 256, SM_ELEMS * sizeof(__nv_bfloat16)>>>(
            xhi, xlo, whi, wlo, qk);
    }
    // 2) fused edge dot + scatter softmax (one warp per node)
    {
        int blocks = (N * 32 + 255) / 256;
        edge_fused_kernel<<<blocks, 256>>>(ei, qk, out, E, N);
    }
}

// round 6
// speedup vs baseline: 1.3175x; 1.3175x over previous
#include <cuda_runtime.h>
#include <cuda_bf16.h>
#include <cuda_pipeline_primitives.h>
#include <mma.h>
#include <stdint.h>

using namespace nvcuda;

// Problem constants (fixed by the dataset)
#define FIN   256
#define FQK   256
#define NQK   (2 * FQK)          // 512
#define MAXN  20000
#define MROWS 20096              // 157 * 128, padded for unguarded tiles
#define SCALING 0.0625f          // FQK^-0.5

// Scratch (no allocation allowed in kernel_launch)
__device__ float g_qk[(size_t)MROWS * NQK];
__device__ __nv_bfloat16 g_xhi[(size_t)MROWS * FIN];
__device__ __nv_bfloat16 g_xlo[(size_t)MROWS * FIN];
__device__ __nv_bfloat16 g_whi[(size_t)NQK * FIN];
__device__ __nv_bfloat16 g_wlo[(size_t)NQK * FIN];

// ===========================================================================
// Kernel 0: split fp32 -> bf16 hi + bf16 lo. One thread per float4.
// ===========================================================================
__global__ __launch_bounds__(256)
void split_kernel(const float* __restrict__ src,
                  __nv_bfloat16* __restrict__ hi,
                  __nv_bfloat16* __restrict__ lo,
                  int n4)
{
    const int i = blockIdx.x * blockDim.x + threadIdx.x;
    if (i >= n4) return;
    float4 v = ((const float4*)src)[i];
    __nv_bfloat16 hx = __float2bfloat16(v.x);
    __nv_bfloat16 hy = __float2bfloat16(v.y);
    __nv_bfloat16 hz = __float2bfloat16(v.z);
    __nv_bfloat16 hw = __float2bfloat16(v.w);
    ((__nv_bfloat162*)hi)[2 * i]     = __halves2bfloat162(hx, hy);
    ((__nv_bfloat162*)hi)[2 * i + 1] = __halves2bfloat162(hz, hw);
    ((__nv_bfloat162*)lo)[2 * i] = __halves2bfloat162(
        __float2bfloat16(v.x - __bfloat162float(hx)),
        __float2bfloat16(v.y - __bfloat162float(hy)));
    ((__nv_bfloat162*)lo)[2 * i + 1] = __halves2bfloat162(
        __float2bfloat16(v.z - __bfloat162float(hz)),
        __float2bfloat16(v.w - __bfloat162float(hw)));
}

// ===========================================================================
// Kernel 1: qk = x @ W^T via WMMA bf16x3 on pre-split inputs, cp.async
// double-buffered. CTA tile 128(m) x 64(n), KC=64, 8 warps (16x64 strip).
// ===========================================================================
#define BM 128
#define BN 64
#define KC 64
#define LDS_ 72                  // padded smem leading dim (bf16), 144B (16B-mult)

// per-stage smem layout (bf16 elements)
#define SA_HI 0
#define SA_LO (SA_HI + BM * LDS_)            // 9216
#define SB_HI (SA_LO + BM * LDS_)            // 18432
#define SB_LO (SB_HI + BN * LDS_)            // 23040
#define STAGE_ELEMS (SB_LO + BN * LDS_)      // 27648 bf16 = 55296 B
#define NSTAGE 2
#define SM_BYTES (STAGE_ELEMS * NSTAGE * 2)  // 110592 B

__device__ __forceinline__ void load_stage(__nv_bfloat16* sm,
                                           const __nv_bfloat16* __restrict__ xhi,
                                           const __nv_bfloat16* __restrict__ xlo,
                                           const __nv_bfloat16* __restrict__ whi,
                                           const __nv_bfloat16* __restrict__ wlo,
                                           int m0, int n0, int kc, int tid)
{
    // A tile: 128 rows x 64 cols -> 1024 x 16B chunks (hi and lo)
#pragma unroll
    for (int i = 0; i < 4; ++i) {
        const int idx = tid + i * 256;           // 0..1023
        const int r = idx >> 3;                  // 0..127
        const int c = (idx & 7) * 8;             // 0..56
        const size_t g = (size_t)(m0 + r) * FIN + kc + c;
        __pipeline_memcpy_async(sm + SA_HI + r * LDS_ + c, xhi + g, 16);
        __pipeline_memcpy_async(sm + SA_LO + r * LDS_ + c, xlo + g, 16);
    }
    // B tile: 64 rows x 64 cols -> 512 x 16B chunks
#pragma unroll
    for (int i = 0; i < 2; ++i) {
        const int idx = tid + i * 256;           // 0..511
        const int r = idx >> 3;                  // 0..63
        const int c = (idx & 7) * 8;
        const size_t g = (size_t)(n0 + r) * FIN + kc + c;
        __pipeline_memcpy_async(sm + SB_HI + r * LDS_ + c, whi + g, 16);
        __pipeline_memcpy_async(sm + SB_LO + r * LDS_ + c, wlo + g, 16);
    }
}

__global__ __launch_bounds__(256)
void gemm_qk_wmma(const __nv_bfloat16* __restrict__ xhi,
                  const __nv_bfloat16* __restrict__ xlo,
                  const __nv_bfloat16* __restrict__ whi,
                  const __nv_bfloat16* __restrict__ wlo,
                  float* __restrict__ qk)
{
    extern __shared__ __nv_bfloat16 sm[];
    const int tid = threadIdx.x;
    const int wid = tid >> 5;
    const int m0  = blockIdx.y * BM;
    const int n0  = blockIdx.x * BN;
    const float scale = (n0 < FQK) ? SCALING : 1.0f;

    wmma::fragment<wmma::accumulator, 16, 16, 16, float> acc[4];
#pragma unroll
    for (int f = 0; f < 4; ++f) wmma::fill_fragment(acc[f], 0.0f);

    // prologue: stage 0 and 1
    load_stage(sm, xhi, xlo, whi, wlo, m0, n0, 0, tid);
    __pipeline_commit();
    load_stage(sm + STAGE_ELEMS, xhi, xlo, whi, wlo, m0, n0, KC, tid);
    __pipeline_commit();

    const int nChunks = FIN / KC;   // 4
    for (int c = 0; c < nChunks; ++c) {
        __pipeline_wait_prior(1);
        __syncthreads();
        __nv_bfloat16* st = sm + (c & 1) * STAGE_ELEMS;

        const __nv_bfloat16* aHi = st + SA_HI + wid * 16 * LDS_;
        const __nv_bfloat16* aLo = st + SA_LO + wid * 16 * LDS_;
#pragma unroll
        for (int ks = 0; ks < KC / 16; ++ks) {
            wmma::fragment<wmma::matrix_a, 16, 16, 16, __nv_bfloat16, wmma::row_major> ah, al;
            wmma::load_matrix_sync(ah, aHi + ks * 16, LDS_);
            wmma::load_matrix_sync(al, aLo + ks * 16, LDS_);
#pragma unroll
            for (int nf = 0; nf < 4; ++nf) {
                wmma::fragment<wmma::matrix_b, 16, 16, 16, __nv_bfloat16, wmma::col_major> bh, bl;
                wmma::load_matrix_sync(bh, st + SB_HI + nf * 16 * LDS_ + ks * 16, LDS_);
                wmma::load_matrix_sync(bl, st + SB_LO + nf * 16 * LDS_ + ks * 16, LDS_);
                wmma::mma_sync(acc[nf], ah, bh, acc[nf]);
                wmma::mma_sync(acc[nf], ah, bl, acc[nf]);
                wmma::mma_sync(acc[nf], al, bh, acc[nf]);
            }
        }
        __syncthreads();
        if (c + 2 < nChunks) {
            load_stage(st, xhi, xlo, whi, wlo, m0, n0, (c + 2) * KC, tid);
        }
        __pipeline_commit();   // keep commit count in lockstep
    }

    // epilogue: scale + store (qk padded to MROWS, unguarded)
#pragma unroll
    for (int nf = 0; nf < 4; ++nf) {
#pragma unroll
        for (int t = 0; t < acc[nf].num_elements; ++t)
            acc[nf].x[t] *= scale;
        float* dst = qk + (size_t)(m0 + wid * 16) * NQK + n0 + nf * 16;
        wmma::store_matrix_sync(dst, acc[nf], NQK, wmma::mem_row_major);
    }
}

// ===========================================================================
// Kernel 2: fused edge pass. One warp per src node, half-warp per edge
// (2 edges/iter), COALESCED stride-16 layout. exp staged in smem.
// ===========================================================================
#define SMEM_DEG 128

__device__ __forceinline__ int lower_bound_i(const int* __restrict__ a,
                                             int n, int v)
{
    int lo = 0, hi = n;
    while (lo < hi) {
        int mid = (lo + hi) >> 1;
        if (a[mid] < v) lo = mid + 1; else hi = mid;
    }
    return lo;
}

__global__ __launch_bounds__(256)
void edge_fused_kernel(const int* __restrict__ ei,
                       const float* __restrict__ qk,
                       float* __restrict__ out,
                       int E, int N)
{
    __shared__ float exbuf[8][SMEM_DEG];

    const int wslot = threadIdx.x >> 5;
    const int node  = (blockIdx.x * blockDim.x + threadIdx.x) >> 5;
    const int lane  = threadIdx.x & 31;
    const int t     = lane & 15;          // k-chunk owner within half-warp
    const int s     = lane >> 4;          // edge slot (0 or 1)
    if (node >= N) return;

    const int lo = lower_bound_i(ei, E, node);
    const int hi = lower_bound_i(ei, E, node + 1);
    const int deg = hi - lo;
    if (deg <= 0) return;

    // q: interleaved float4s (lane t reads qp[t], qp[t+16], qp[t+32], qp[t+48])
    const float4* qp = (const float4*)(qk + (size_t)node * NQK);
    float4 qr[4];
#pragma unroll
    for (int i = 0; i < 4; ++i) qr[i] = qp[t + 16 * i];

    const int* __restrict__ dest = ei + E;
    const int nIter = (deg + 1) >> 1;
    float sum = 0.0f;

    if (deg <= SMEM_DEG) {
        for (int it = 0; it < nIter; ++it) {
            const int j = lo + 2 * it + s;
            const int jj = (j < hi) ? j : (hi - 1);
            const int d = dest[jj];
            const float4* kp = (const float4*)(qk + (size_t)d * NQK + FQK);
            float p = 0.0f;
#pragma unroll
            for (int i = 0; i < 4; ++i) {
                float4 kv = kp[t + 16 * i];
                p += qr[i].x * kv.x + qr[i].y * kv.y
                   + qr[i].z * kv.z + qr[i].w * kv.w;
            }
#pragma unroll
            for (int o = 1; o < 16; o <<= 1)
                p += __shfl_xor_sync(0xffffffffu, p, o);

            float ex = __expf(p);
            if (j < hi) {
                sum += ex;
                if (t == 0) exbuf[wslot][j - lo] = ex;
            }
        }
        sum += __shfl_xor_sync(0xffffffffu, sum, 16);
        const float inv = 1.0f / sum;
        __syncwarp();
        for (int i = lane; i < deg; i += 32)
            out[lo + i] = exbuf[wslot][i] * inv;
    } else {
        // fallback for very high degree: stage in gmem, two passes
        for (int it = 0; it < nIter; ++it) {
            const int j = lo + 2 * it + s;
            const int jj = (j < hi) ? j : (hi - 1);
            const int d = dest[jj];
            const float4* kp = (const float4*)(qk + (size_t)d * NQK + FQK);
            float p = 0.0f;
#pragma unroll
            for (int i = 0; i < 4; ++i) {
                float4 kv = kp[t + 16 * i];
                p += qr[i].x * kv.x + qr[i].y * kv.y
                   + qr[i].z * kv.z + qr[i].w * kv.w;
            }
#pragma unroll
            for (int o = 1; o < 16; o <<= 1)
                p += __shfl_xor_sync(0xffffffffu, p, o);
            float ex = __expf(p);
            if (j < hi) {
                sum += ex;
                if (t == 0) out[j] = ex;
            }
        }
        sum += __shfl_xor_sync(0xffffffffu, sum, 16);
        const float inv = 1.0f / sum;
        __threadfence_block();
        __syncwarp();
        for (int i = lane; i < deg; i += 32)
            out[lo + i] *= inv;
    }
}

// ===========================================================================
extern "C" void kernel_launch(void* const* d_in, const int* in_sizes, int n_in,
                              void* d_out, int out_size)
{
    const float* x   = (const float*)d_in[0];
    const int*   ei  = (const int*)d_in[1];
    const float* W   = (const float*)d_in[2];
    float*       out = (float*)d_out;

    const int N = in_sizes[0] / FIN;     // 20000
    const int E = in_sizes[1] / 2;       // 640000

    float* qk;          cudaGetSymbolAddress((void**)&qk,  g_qk);
    __nv_bfloat16* xhi; cudaGetSymbolAddress((void**)&xhi, g_xhi);
    __nv_bfloat16* xlo; cudaGetSymbolAddress((void**)&xlo, g_xlo);
    __nv_bfloat16* whi; cudaGetSymbolAddress((void**)&whi, g_whi);
    __nv_bfloat16* wlo; cudaGetSymbolAddress((void**)&wlo, g_wlo);

    // 0) split fp32 -> bf16 hi/lo (x and W)
    {
        int n4x = N * FIN / 4;
        split_kernel<<<(n4x + 255) / 256, 256>>>(x, xhi, xlo, n4x);
        int n4w = NQK * FIN / 4;
        split_kernel<<<(n4w + 255) / 256, 256>>>(W, whi, wlo, n4w);
    }
    // 1) projection GEMM (bf16x3 WMMA, cp.async double-buffered)
    {
        cudaFuncSetAttribute(gemm_qk_wmma,
                             cudaFuncAttributeMaxDynamicSharedMemorySize,
                             SM_BYTES);
        dim3 grid(NQK / BN, MROWS / BM);
        gemm_qk_wmma<<<grid, 256, SM_BYTES>>>(xhi, xlo, whi, wlo, qk);
    }
    // 2) fused edge dot + scatter softmax (one warp per node)
    {
        int blocks = (N * 32 + 255) / 256;
        edge_fused_kernel<<<blocks, 256>>>(ei, qk, out, E, N);
    }
}

// round 7
// speedup vs baseline: 1.9502x; 1.4802x over previous
#include <cuda_runtime.h>
#include <cuda_fp16.h>
#include <cuda_pipeline_primitives.h>
#include <mma.h>
#include <stdint.h>

using namespace nvcuda;

// Problem constants (fixed by the dataset)
#define FIN   256
#define FQK   256
#define NQK   (2 * FQK)          // 512
#define MAXN  20000
#define MROWS 20096              // 157 * 128, padded for unguarded tiles
#define SCALING 0.0625f          // FQK^-0.5

// Scratch (no allocation allowed in kernel_launch)
__device__ float  g_q [(size_t)MROWS * FQK];     // q half, fp32
__device__ __half g_kh[(size_t)MROWS * FQK];     // k half, fp16
__device__ __half g_xhi[(size_t)MROWS * FIN];
__device__ __half g_xlo[(size_t)MROWS * FIN];
__device__ __half g_wh [(size_t)NQK * FIN];

// ===========================================================================
// Kernel 0a: split fp32 -> fp16 hi + fp16 lo. One thread per float4.
// ===========================================================================
__global__ __launch_bounds__(256)
void split_kernel(const float* __restrict__ src,
                  __half* __restrict__ hi,
                  __half* __restrict__ lo,
                  int n4)
{
    const int i = blockIdx.x * blockDim.x + threadIdx.x;
    if (i >= n4) return;
    float4 v = ((const float4*)src)[i];
    __half hx = __float2half(v.x);
    __half hy = __float2half(v.y);
    __half hz = __float2half(v.z);
    __half hw = __float2half(v.w);
    ((__half2*)hi)[2 * i]     = __halves2half2(hx, hy);
    ((__half2*)hi)[2 * i + 1] = __halves2half2(hz, hw);
    ((__half2*)lo)[2 * i] = __halves2half2(
        __float2half(v.x - __half2float(hx)),
        __float2half(v.y - __half2float(hy)));
    ((__half2*)lo)[2 * i + 1] = __halves2half2(
        __float2half(v.z - __half2float(hz)),
        __float2half(v.w - __half2float(hw)));
}

// Kernel 0b: plain fp32 -> fp16 convert (for W)
__global__ __launch_bounds__(256)
void convert_kernel(const float* __restrict__ src,
                    __half* __restrict__ dst,
                    int n4)
{
    const int i = blockIdx.x * blockDim.x + threadIdx.x;
    if (i >= n4) return;
    float4 v = ((const float4*)src)[i];
    ((__half2*)dst)[2 * i]     = __halves2half2(__float2half(v.x), __float2half(v.y));
    ((__half2*)dst)[2 * i + 1] = __halves2half2(__float2half(v.z), __float2half(v.w));
}

// ===========================================================================
// Kernel 1: qk = x @ W^T via WMMA fp16x2 (A split hi/lo, B single fp16).
// CTA tile 128(m) x 64(n), KC=64, 8 warps (16x64 strip each), cp.async x2.
// q tiles (n0<256): scaled fp32 store. k tiles: fp16 store via smem.
// ===========================================================================
#define BM 128
#define BN 64
#define KC 64
#define LDS_ 72                  // padded smem leading dim (halves)

// per-stage smem layout (half elements)
#define SA_HI 0
#define SA_LO (SA_HI + BM * LDS_)            // 9216
#define SB_   (SA_LO + BM * LDS_)            // 18432
#define STAGE_ELEMS (SB_ + BN * LDS_)        // 23040 halves = 46080 B
#define NSTAGE 2
#define SM_BYTES (STAGE_ELEMS * NSTAGE * 2)  // 92160 B

__device__ __forceinline__ void load_stage(__half* sm,
                                           const __half* __restrict__ xhi,
                                           const __half* __restrict__ xlo,
                                           const __half* __restrict__ wh,
                                           int m0, int n0, int kc, int tid)
{
    // A tile: 128 rows x 64 halves (128 B/row -> 8 x 16B chunks)
#pragma unroll
    for (int i = 0; i < 4; ++i) {
        const int idx = tid + i * 256;           // 0..1023
        const int r = idx >> 3;                  // 0..127
        const int c = (idx & 7) * 8;             // 0..56
        const size_t g = (size_t)(m0 + r) * FIN + kc + c;
        __pipeline_memcpy_async(sm + SA_HI + r * LDS_ + c, xhi + g, 16);
        __pipeline_memcpy_async(sm + SA_LO + r * LDS_ + c, xlo + g, 16);
    }
    // B tile: 64 rows x 64 halves
#pragma unroll
    for (int i = 0; i < 2; ++i) {
        const int idx = tid + i * 256;           // 0..511
        const int r = idx >> 3;                  // 0..63
        const int c = (idx & 7) * 8;
        const size_t g = (size_t)(n0 + r) * FIN + kc + c;
        __pipeline_memcpy_async(sm + SB_ + r * LDS_ + c, wh + g, 16);
    }
}

__global__ __launch_bounds__(256)
void gemm_qk_wmma(const __half* __restrict__ xhi,
                  const __half* __restrict__ xlo,
                  const __half* __restrict__ wh,
                  float* __restrict__ qout,
                  __half* __restrict__ kout)
{
    extern __shared__ __half sm[];
    const int tid = threadIdx.x;
    const int wid = tid >> 5;
    const int lane = tid & 31;
    const int m0  = blockIdx.y * BM;
    const int n0  = blockIdx.x * BN;

    wmma::fragment<wmma::accumulator, 16, 16, 16, float> acc[4];
#pragma unroll
    for (int f = 0; f < 4; ++f) wmma::fill_fragment(acc[f], 0.0f);

    load_stage(sm, xhi, xlo, wh, m0, n0, 0, tid);
    __pipeline_commit();
    load_stage(sm + STAGE_ELEMS, xhi, xlo, wh, m0, n0, KC, tid);
    __pipeline_commit();

    const int nChunks = FIN / KC;   // 4
    for (int c = 0; c < nChunks; ++c) {
        __pipeline_wait_prior(1);
        __syncthreads();
        __half* st = sm + (c & 1) * STAGE_ELEMS;

        const __half* aHi = st + SA_HI + wid * 16 * LDS_;
        const __half* aLo = st + SA_LO + wid * 16 * LDS_;
#pragma unroll
        for (int ks = 0; ks < KC / 16; ++ks) {
            wmma::fragment<wmma::matrix_a, 16, 16, 16, __half, wmma::row_major> ah, al;
            wmma::load_matrix_sync(ah, aHi + ks * 16, LDS_);
            wmma::load_matrix_sync(al, aLo + ks * 16, LDS_);
#pragma unroll
            for (int nf = 0; nf < 4; ++nf) {
                wmma::fragment<wmma::matrix_b, 16, 16, 16, __half, wmma::col_major> bh;
                wmma::load_matrix_sync(bh, st + SB_ + nf * 16 * LDS_ + ks * 16, LDS_);
                wmma::mma_sync(acc[nf], ah, bh, acc[nf]);
                wmma::mma_sync(acc[nf], al, bh, acc[nf]);
            }
        }
        __syncthreads();
        if (c + 2 < nChunks) {
            load_stage(st, xhi, xlo, wh, m0, n0, (c + 2) * KC, tid);
        }
        __pipeline_commit();
    }

    if (n0 < FQK) {
        // q tile: scale and store fp32
#pragma unroll
        for (int nf = 0; nf < 4; ++nf) {
#pragma unroll
            for (int t = 0; t < acc[nf].num_elements; ++t)
                acc[nf].x[t] *= SCALING;
            float* dst = qout + (size_t)(m0 + wid * 16) * FQK + n0 + nf * 16;
            wmma::store_matrix_sync(dst, acc[nf], FQK, wmma::mem_row_major);
        }
    } else {
        // k tile: round-trip through smem, convert to fp16
        __syncthreads();
        float* buf = (float*)sm + wid * (16 * 64);   // 4 KB per warp
#pragma unroll
        for (int nf = 0; nf < 4; ++nf)
            wmma::store_matrix_sync(buf + nf * 16, acc[nf], 64, wmma::mem_row_major);
        __syncwarp();
        const int row0 = m0 + wid * 16;
        const int col0 = n0 - FQK;
#pragma unroll
        for (int r = 0; r < 16; ++r) {
            float a = buf[r * 64 + 2 * lane];
            float b = buf[r * 64 + 2 * lane + 1];
            ((__half2*)(kout + (size_t)(row0 + r) * FQK + col0))[lane] =
                __halves2half2(__float2half(a), __float2half(b));
        }
    }
}

// ===========================================================================
// Kernel 2: fused edge pass. One warp per src node, half-warp per edge
// (2 edges/iter). q fp32 in regs; k gathered as fp16 (512 B/edge).
// ===========================================================================
#define SMEM_DEG 128

__device__ __forceinline__ int lower_bound_i(const int* __restrict__ a,
                                             int n, int v)
{
    int lo = 0, hi = n;
    while (lo < hi) {
        int mid = (lo + hi) >> 1;
        if (a[mid] < v) lo = mid + 1; else hi = mid;
    }
    return lo;
}

__device__ __forceinline__ float dot16(const float4* qr, uint4 kv0, uint4 kv1)
{
    float p = 0.0f;
    const uint32_t* kw0 = (const uint32_t*)&kv0;
    const uint32_t* kw1 = (const uint32_t*)&kv1;
#pragma unroll
    for (int h = 0; h < 4; ++h) {
        float2 f0 = __half22float2(*(const __half2*)&kw0[h]);
        const float* q0 = (const float*)&qr[h >> 1] + (h & 1) * 2;
        p += q0[0] * f0.x + q0[1] * f0.y;
    }
#pragma unroll
    for (int h = 0; h < 4; ++h) {
        float2 f1 = __half22float2(*(const __half2*)&kw1[h]);
        const float* q1 = (const float*)&qr[2 + (h >> 1)] + (h & 1) * 2;
        p += q1[0] * f1.x + q1[1] * f1.y;
    }
    return p;
}

__global__ __launch_bounds__(256)
void edge_fused_kernel(const int* __restrict__ ei,
                       const float* __restrict__ q,
                       const __half* __restrict__ kh,
                       float* __restrict__ out,
                       int E, int N)
{
    __shared__ float exbuf[8][SMEM_DEG];

    const int wslot = threadIdx.x >> 5;
    const int node  = (blockIdx.x * blockDim.x + threadIdx.x) >> 5;
    const int lane  = threadIdx.x & 31;
    const int t     = lane & 15;          // k-chunk owner within half-warp
    const int s     = lane >> 4;          // edge slot (0 or 1)
    if (node >= N) return;

    const int lo = lower_bound_i(ei, E, node);
    const int hi = lower_bound_i(ei, E, node + 1);
    const int deg = hi - lo;
    if (deg <= 0) return;

    // lane t owns k-cols [8t, 8t+8) and [8(t+16), 8(t+16)+8)
    const float4* qp = (const float4*)(q + (size_t)node * FQK);
    float4 qr[4];
    qr[0] = qp[2 * t];
    qr[1] = qp[2 * t + 1];
    qr[2] = qp[2 * (t + 16)];
    qr[3] = qp[2 * (t + 16) + 1];

    const int* __restrict__ dest = ei + E;
    const int nIter = (deg + 1) >> 1;
    float sum = 0.0f;

    if (deg <= SMEM_DEG) {
        for (int it = 0; it < nIter; ++it) {
            const int j = lo + 2 * it + s;
            const int jj = (j < hi) ? j : (hi - 1);
            const int d = dest[jj];
            const uint4* kp = (const uint4*)(kh + (size_t)d * FQK);
            uint4 kv0 = kp[t];
            uint4 kv1 = kp[t + 16];
            float p = dot16(qr, kv0, kv1);
#pragma unroll
            for (int o = 1; o < 16; o <<= 1)
                p += __shfl_xor_sync(0xffffffffu, p, o);

            float ex = __expf(p);
            if (j < hi) {
                sum += ex;
                if (t == 0) exbuf[wslot][j - lo] = ex;
            }
        }
        sum += __shfl_xor_sync(0xffffffffu, sum, 16);
        const float inv = 1.0f / sum;
        __syncwarp();
        for (int i = lane; i < deg; i += 32)
            out[lo + i] = exbuf[wslot][i] * inv;
    } else {
        // fallback for very high degree: stage in gmem, two passes
        for (int it = 0; it < nIter; ++it) {
            const int j = lo + 2 * it + s;
            const int jj = (j < hi) ? j : (hi - 1);
            const int d = dest[jj];
            const uint4* kp = (const uint4*)(kh + (size_t)d * FQK);
            uint4 kv0 = kp[t];
            uint4 kv1 = kp[t + 16];
            float p = dot16(qr, kv0, kv1);
#pragma unroll
            for (int o = 1; o < 16; o <<= 1)
                p += __shfl_xor_sync(0xffffffffu, p, o);
            float ex = __expf(p);
            if (j < hi) {
                sum += ex;
                if (t == 0) out[j] = ex;
            }
        }
        sum += __shfl_xor_sync(0xffffffffu, sum, 16);
        const float inv = 1.0f / sum;
        __threadfence_block();
        __syncwarp();
        for (int i = lane; i < deg; i += 32)
            out[lo + i] *= inv;
    }
}

// ===========================================================================
extern "C" void kernel_launch(void* const* d_in, const int* in_sizes, int n_in,
                              void* d_out, int out_size)
{
    const float* x   = (const float*)d_in[0];
    const int*   ei  = (const int*)d_in[1];
    const float* W   = (const float*)d_in[2];
    float*       out = (float*)d_out;

    const int N = in_sizes[0] / FIN;     // 20000
    const int E = in_sizes[1] / 2;       // 640000

    float*  q;   cudaGetSymbolAddress((void**)&q,   g_q);
    __half* kht; cudaGetSymbolAddress((void**)&kht, g_kh);
    __half* xhi; cudaGetSymbolAddress((void**)&xhi, g_xhi);
    __half* xlo; cudaGetSymbolAddress((void**)&xlo, g_xlo);
    __half* wh;  cudaGetSymbolAddress((void**)&wh,  g_wh);

    // 0) split x -> fp16 hi/lo; convert W -> fp16
    {
        int n4x = N * FIN / 4;
        split_kernel<<<(n4x + 255) / 256, 256>>>(x, xhi, xlo, n4x);
        int n4w = NQK * FIN / 4;
        convert_kernel<<<(n4w + 255) / 256, 256>>>(W, wh, n4w);
    }
    // 1) projection GEMM (fp16x2 WMMA, cp.async double-buffered)
    {
        cudaFuncSetAttribute(gemm_qk_wmma,
                             cudaFuncAttributeMaxDynamicSharedMemorySize,
                             SM_BYTES);
        dim3 grid(NQK / BN, MROWS / BM);
        gemm_qk_wmma<<<grid, 256, SM_BYTES>>>(xhi, xlo, wh, q, kht);
    }
    // 2) fused edge dot + scatter softmax (one warp per node)
    {
        int blocks = (N * 32 + 255) / 256;
        edge_fused_kernel<<<blocks, 256>>>(ei, q, kht, out, E, N);
    }
}

// round 8
// speedup vs baseline: 2.1298x; 1.0921x over previous
#include <cuda_runtime.h>
#include <cuda_fp16.h>
#include <cuda_pipeline_primitives.h>
#include <mma.h>
#include <stdint.h>

using namespace nvcuda;

// Problem constants (fixed by the dataset)
#define FIN   256
#define FQK   256
#define NQK   (2 * FQK)          // 512
#define MAXN  20000
#define MROWS 20096              // 157 * 128, padded for unguarded tiles
#define SCALING 0.0625f          // FQK^-0.5

// Scratch (no allocation allowed in kernel_launch)
__device__ __half g_qh[(size_t)MROWS * FQK];     // q half, fp16 (scaled)
__device__ __half g_kh[(size_t)MROWS * FQK];     // k half, fp16
__device__ __half g_xhi[(size_t)MROWS * FIN];
__device__ __half g_xlo[(size_t)MROWS * FIN];
__device__ __half g_wh [(size_t)NQK * FIN];

// ===========================================================================
// Kernel 0a: split fp32 -> fp16 hi + fp16 lo. One thread per float4.
// ===========================================================================
__global__ __launch_bounds__(256)
void split_kernel(const float* __restrict__ src,
                  __half* __restrict__ hi,
                  __half* __restrict__ lo,
                  int n4)
{
    const int i = blockIdx.x * blockDim.x + threadIdx.x;
    if (i >= n4) return;
    float4 v = ((const float4*)src)[i];
    __half hx = __float2half(v.x);
    __half hy = __float2half(v.y);
    __half hz = __float2half(v.z);
    __half hw = __float2half(v.w);
    ((__half2*)hi)[2 * i]     = __halves2half2(hx, hy);
    ((__half2*)hi)[2 * i + 1] = __halves2half2(hz, hw);
    ((__half2*)lo)[2 * i] = __halves2half2(
        __float2half(v.x - __half2float(hx)),
        __float2half(v.y - __half2float(hy)));
    ((__half2*)lo)[2 * i + 1] = __halves2half2(
        __float2half(v.z - __half2float(hz)),
        __float2half(v.w - __half2float(hw)));
}

// Kernel 0b: plain fp32 -> fp16 convert (for W)
__global__ __launch_bounds__(256)
void convert_kernel(const float* __restrict__ src,
                    __half* __restrict__ dst,
                    int n4)
{
    const int i = blockIdx.x * blockDim.x + threadIdx.x;
    if (i >= n4) return;
    float4 v = ((const float4*)src)[i];
    ((__half2*)dst)[2 * i]     = __halves2half2(__float2half(v.x), __float2half(v.y));
    ((__half2*)dst)[2 * i + 1] = __halves2half2(__float2half(v.z), __float2half(v.w));
}

// ===========================================================================
// Kernel 1: qk = x @ W^T via WMMA fp16x2 (A split hi/lo, B single fp16).
// CTA tile 128(m) x 128(n), KC=64, 8 warps as 4x2 (warp = 32x64 strip),
// cp.async double-buffered. Output fp16 (q scaled, k plain).
// ===========================================================================
#define BM 128
#define BN 128
#define KC 64
#define LDS_ 72                  // padded smem leading dim (halves)

// per-stage smem layout (half elements)
#define SA_HI 0
#define SA_LO (SA_HI + BM * LDS_)            // 9216
#define SB_   (SA_LO + BM * LDS_)            // 18432
#define STAGE_ELEMS (SB_ + BN * LDS_)        // 27648 halves = 55296 B
#define NSTAGE 2
#define SM_BYTES (STAGE_ELEMS * NSTAGE * 2)  // 110592 B

__device__ __forceinline__ void load_stage(__half* sm,
                                           const __half* __restrict__ xhi,
                                           const __half* __restrict__ xlo,
                                           const __half* __restrict__ wh,
                                           int m0, int n0, int kc, int tid)
{
    // A tile: 128 rows x 64 halves (8 x 16B chunks per row)
#pragma unroll
    for (int i = 0; i < 4; ++i) {
        const int idx = tid + i * 256;           // 0..1023
        const int r = idx >> 3;                  // 0..127
        const int c = (idx & 7) * 8;             // 0..56
        const size_t g = (size_t)(m0 + r) * FIN + kc + c;
        __pipeline_memcpy_async(sm + SA_HI + r * LDS_ + c, xhi + g, 16);
        __pipeline_memcpy_async(sm + SA_LO + r * LDS_ + c, xlo + g, 16);
    }
    // B tile: 128 rows x 64 halves
#pragma unroll
    for (int i = 0; i < 4; ++i) {
        const int idx = tid + i * 256;           // 0..1023
        const int r = idx >> 3;                  // 0..127
        const int c = (idx & 7) * 8;
        const size_t g = (size_t)(n0 + r) * FIN + kc + c;
        __pipeline_memcpy_async(sm + SB_ + r * LDS_ + c, wh + g, 16);
    }
}

__global__ __launch_bounds__(256)
void gemm_qk_wmma(const __half* __restrict__ xhi,
                  const __half* __restrict__ xlo,
                  const __half* __restrict__ wh,
                  __half* __restrict__ qout,
                  __half* __restrict__ kout)
{
    extern __shared__ __half sm[];
    const int tid = threadIdx.x;
    const int wid = tid >> 5;
    const int lane = tid & 31;
    const int warp_m = wid >> 1;          // 0..3
    const int warp_n = wid & 1;           // 0..1
    const int m0  = blockIdx.y * BM;
    const int n0  = blockIdx.x * BN;
    const bool is_q = (n0 < FQK);
    const float scale = is_q ? SCALING : 1.0f;

    wmma::fragment<wmma::accumulator, 16, 16, 16, float> acc[2][4];
#pragma unroll
    for (int mi = 0; mi < 2; ++mi)
#pragma unroll
        for (int f = 0; f < 4; ++f) wmma::fill_fragment(acc[mi][f], 0.0f);

    load_stage(sm, xhi, xlo, wh, m0, n0, 0, tid);
    __pipeline_commit();
    load_stage(sm + STAGE_ELEMS, xhi, xlo, wh, m0, n0, KC, tid);
    __pipeline_commit();

    const int nChunks = FIN / KC;   // 4
    for (int c = 0; c < nChunks; ++c) {
        __pipeline_wait_prior(1);
        __syncthreads();
        __half* st = sm + (c & 1) * STAGE_ELEMS;

#pragma unroll
        for (int ks = 0; ks < KC / 16; ++ks) {
            wmma::fragment<wmma::matrix_a, 16, 16, 16, __half, wmma::row_major> ah[2], al[2];
#pragma unroll
            for (int mi = 0; mi < 2; ++mi) {
                const int row = warp_m * 32 + mi * 16;
                wmma::load_matrix_sync(ah[mi], st + SA_HI + row * LDS_ + ks * 16, LDS_);
                wmma::load_matrix_sync(al[mi], st + SA_LO + row * LDS_ + ks * 16, LDS_);
            }
#pragma unroll
            for (int nf = 0; nf < 4; ++nf) {
                const int col = warp_n * 64 + nf * 16;
                wmma::fragment<wmma::matrix_b, 16, 16, 16, __half, wmma::col_major> bh;
                wmma::load_matrix_sync(bh, st + SB_ + col * LDS_ + ks * 16, LDS_);
#pragma unroll
                for (int mi = 0; mi < 2; ++mi) {
                    wmma::mma_sync(acc[mi][nf], ah[mi], bh, acc[mi][nf]);
                    wmma::mma_sync(acc[mi][nf], al[mi], bh, acc[mi][nf]);
                }
            }
        }
        __syncthreads();
        if (c + 2 < nChunks) {
            load_stage(st, xhi, xlo, wh, m0, n0, (c + 2) * KC, tid);
        }
        __pipeline_commit();
    }

    // ---- epilogue: fp32 acc -> fp16 via per-warp smem scratch ----
    __syncthreads();   // all MMA reads of stage smem done; reuse as scratch
    float* buf = (float*)sm + wid * (16 * 64);   // 4 KB per warp
    __half* outp = is_q ? qout : kout;
    const int col0 = (is_q ? n0 : n0 - FQK) + warp_n * 64;

#pragma unroll
    for (int mi = 0; mi < 2; ++mi) {
        const int row0 = m0 + warp_m * 32 + mi * 16;
#pragma unroll
        for (int nf = 0; nf < 4; ++nf) {
#pragma unroll
            for (int t = 0; t < acc[mi][nf].num_elements; ++t)
                acc[mi][nf].x[t] *= scale;
            wmma::store_matrix_sync(buf + nf * 16, acc[mi][nf], 64, wmma::mem_row_major);
        }
        __syncwarp();
#pragma unroll
        for (int r = 0; r < 16; ++r) {
            float a = buf[r * 64 + 2 * lane];
            float b = buf[r * 64 + 2 * lane + 1];
            ((__half2*)(outp + (size_t)(row0 + r) * FQK + col0))[lane] =
                __halves2half2(__float2half(a), __float2half(b));
        }
        __syncwarp();
    }
}

// ===========================================================================
// Kernel 2: fused edge pass. One warp per src node, half-warp per edge
// (2 edges/iter). q,k fp16; dot via HFMA2, reduce in fp32. Pipelined gather.
// ===========================================================================
#define SMEM_DEG 128

__device__ __forceinline__ int lower_bound_i(const int* __restrict__ a,
                                             int n, int v)
{
    int lo = 0, hi = n;
    while (lo < hi) {
        int mid = (lo + hi) >> 1;
        if (a[mid] < v) lo = mid + 1; else hi = mid;
    }
    return lo;
}

__device__ __forceinline__ float dot_h2(uint4 q0, uint4 q1, uint4 k0, uint4 k1)
{
    const __half2* qa = (const __half2*)&q0;
    const __half2* qb = (const __half2*)&q1;
    const __half2* ka = (const __half2*)&k0;
    const __half2* kb = (const __half2*)&k1;
    __half2 acc = __hmul2(qa[0], ka[0]);
#pragma unroll
    for (int i = 1; i < 4; ++i) acc = __hfma2(qa[i], ka[i], acc);
#pragma unroll
    for (int i = 0; i < 4; ++i) acc = __hfma2(qb[i], kb[i], acc);
    float2 f = __half22float2(acc);
    return f.x + f.y;
}

__global__ __launch_bounds__(256)
void edge_fused_kernel(const int* __restrict__ ei,
                       const __half* __restrict__ qh,
                       const __half* __restrict__ kh,
                       float* __restrict__ out,
                       int E, int N)
{
    __shared__ float exbuf[8][SMEM_DEG];

    const int wslot = threadIdx.x >> 5;
    const int node  = (blockIdx.x * blockDim.x + threadIdx.x) >> 5;
    const int lane  = threadIdx.x & 31;
    const int t     = lane & 15;          // k-chunk owner within half-warp
    const int s     = lane >> 4;          // edge slot (0 or 1)
    if (node >= N) return;

    const int lo = lower_bound_i(ei, E, node);
    const int hi = lower_bound_i(ei, E, node + 1);
    const int deg = hi - lo;
    if (deg <= 0) return;

    // lane t owns cols [8t, 8t+8) and [128+8t, 128+8t+8)
    const uint4* qp = (const uint4*)(qh + (size_t)node * FQK);
    const uint4 q0 = qp[t];
    const uint4 q1 = qp[t + 16];

    const int* __restrict__ dest = ei + E;
    const int nIter = (deg + 1) >> 1;
    float sum = 0.0f;

    if (deg <= SMEM_DEG) {
        // prime the pipeline
        int j = lo + s;
        int jj = (j < hi) ? j : (hi - 1);
        const uint4* kp = (const uint4*)(kh + (size_t)dest[jj] * FQK);
        uint4 k0 = kp[t];
        uint4 k1 = kp[t + 16];

        for (int it = 0; it < nIter; ++it) {
            uint4 c0 = k0, c1 = k1;
            const int jn = j + 2;
            if (jn < hi) {
                const uint4* kn = (const uint4*)(kh + (size_t)dest[jn] * FQK);
                k0 = kn[t];
                k1 = kn[t + 16];
            }
            float p = dot_h2(q0, q1, c0, c1);
#pragma unroll
            for (int o = 1; o < 16; o <<= 1)
                p += __shfl_xor_sync(0xffffffffu, p, o);

            float ex = __expf(p);
            if (j < hi) {
                sum += ex;
                if (t == 0) exbuf[wslot][j - lo] = ex;
            }
            j = jn;
        }
        sum += __shfl_xor_sync(0xffffffffu, sum, 16);
        const float inv = 1.0f / sum;
        __syncwarp();
        for (int i = lane; i < deg; i += 32)
            out[lo + i] = exbuf[wslot][i] * inv;
    } else {
        // fallback for very high degree: stage in gmem, two passes
        for (int it = 0; it < nIter; ++it) {
            const int j = lo + 2 * it + s;
            const int jj = (j < hi) ? j : (hi - 1);
            const uint4* kp = (const uint4*)(kh + (size_t)dest[jj] * FQK);
            uint4 c0 = kp[t];
            uint4 c1 = kp[t + 16];
            float p = dot_h2(q0, q1, c0, c1);
#pragma unroll
            for (int o = 1; o < 16; o <<= 1)
                p += __shfl_xor_sync(0xffffffffu, p, o);
            float ex = __expf(p);
            if (j < hi) {
                sum += ex;
                if (t == 0) out[j] = ex;
            }
        }
        sum += __shfl_xor_sync(0xffffffffu, sum, 16);
        const float inv = 1.0f / sum;
        __threadfence_block();
        __syncwarp();
        for (int i = lane; i < deg; i += 32)
            out[lo + i] *= inv;
    }
}

// ===========================================================================
extern "C" void kernel_launch(void* const* d_in, const int* in_sizes, int n_in,
                              void* d_out, int out_size)
{
    const float* x   = (const float*)d_in[0];
    const int*   ei  = (const int*)d_in[1];
    const float* W   = (const float*)d_in[2];
    float*       out = (float*)d_out;

    const int N = in_sizes[0] / FIN;     // 20000
    const int E = in_sizes[1] / 2;       // 640000

    __half* qht; cudaGetSymbolAddress((void**)&qht, g_qh);
    __half* kht; cudaGetSymbolAddress((void**)&kht, g_kh);
    __half* xhi; cudaGetSymbolAddress((void**)&xhi, g_xhi);
    __half* xlo; cudaGetSymbolAddress((void**)&xlo, g_xlo);
    __half* wh;  cudaGetSymbolAddress((void**)&wh,  g_wh);

    // 0) split x -> fp16 hi/lo; convert W -> fp16
    {
        int n4x = N * FIN / 4;
        split_kernel<<<(n4x + 255) / 256, 256>>>(x, xhi, xlo, n4x);
        int n4w = NQK * FIN / 4;
        convert_kernel<<<(n4w + 255) / 256, 256>>>(W, wh, n4w);
    }
    // 1) projection GEMM (fp16x2 WMMA, cp.async double-buffered)
    {
        cudaFuncSetAttribute(gemm_qk_wmma,
                             cudaFuncAttributeMaxDynamicSharedMemorySize,
                             SM_BYTES);
        dim3 grid(NQK / BN, MROWS / BM);
        gemm_qk_wmma<<<grid, 256, SM_BYTES>>>(xhi, xlo, wh, qht, kht);
    }
    // 2) fused edge dot + scatter softmax (one warp per node)
    {
        int blocks = (N * 32 + 255) / 256;
        edge_fused_kernel<<<blocks, 256>>>(ei, qht, kht, out, E, N);
    }
}

// round 9
// speedup vs baseline: 2.6300x; 1.2349x over previous
#include <cuda_runtime.h>
#include <cuda_fp16.h>
#include <cuda_pipeline_primitives.h>
#include <mma.h>
#include <stdint.h>

using namespace nvcuda;

// Problem constants (fixed by the dataset)
#define FIN   256
#define FQK   256
#define NQK   (2 * FQK)          // 512
#define MAXN  20000
#define MROWS 20096              // 157 * 128, padded for unguarded tiles
#define SCALING 0.0625f          // FQK^-0.5

// Scratch (no allocation allowed in kernel_launch)
__device__ __half g_qh[(size_t)MROWS * FQK];     // q half, fp16 (scaled)
__device__ __half g_kh[(size_t)MROWS * FQK];     // k half, fp16
__device__ __half g_xh[(size_t)MROWS * FIN];     // x in fp16
__device__ __half g_wh[(size_t)NQK * FIN];       // W in fp16

// ===========================================================================
// Kernel 0: fp32 -> fp16 convert. One thread per float4.
// ===========================================================================
__global__ __launch_bounds__(256)
void convert_kernel(const float* __restrict__ src,
                    __half* __restrict__ dst,
                    int n4)
{
    const int i = blockIdx.x * blockDim.x + threadIdx.x;
    if (i >= n4) return;
    float4 v = ((const float4*)src)[i];
    ((__half2*)dst)[2 * i]     = __halves2half2(__float2half(v.x), __float2half(v.y));
    ((__half2*)dst)[2 * i + 1] = __halves2half2(__float2half(v.z), __float2half(v.w));
}

// ===========================================================================
// Kernel 1: qk = x @ W^T via WMMA fp16. CTA tile 128(m) x 128(n), KC=64,
// 8 warps as 4x2 (warp = 32x64 strip), cp.async double-buffered.
// Output fp16 (q scaled, k plain).
// ===========================================================================
#define BM 128
#define BN 128
#define KC 64
#define LDS_ 72                  // padded smem leading dim (halves)

// per-stage smem layout (half elements)
#define SA_   0
#define SB_   (SA_ + BM * LDS_)              // 9216
#define STAGE_ELEMS (SB_ + BN * LDS_)        // 18432 halves = 36864 B
#define NSTAGE 2
#define SM_BYTES (STAGE_ELEMS * NSTAGE * 2)  // 73728 B

__device__ __forceinline__ void load_stage(__half* sm,
                                           const __half* __restrict__ xh,
                                           const __half* __restrict__ wh,
                                           int m0, int n0, int kc, int tid)
{
    // A tile: 128 rows x 64 halves (8 x 16B chunks per row)
#pragma unroll
    for (int i = 0; i < 4; ++i) {
        const int idx = tid + i * 256;           // 0..1023
        const int r = idx >> 3;                  // 0..127
        const int c = (idx & 7) * 8;             // 0..56
        const size_t g = (size_t)(m0 + r) * FIN + kc + c;
        __pipeline_memcpy_async(sm + SA_ + r * LDS_ + c, xh + g, 16);
    }
    // B tile: 128 rows x 64 halves
#pragma unroll
    for (int i = 0; i < 4; ++i) {
        const int idx = tid + i * 256;
        const int r = idx >> 3;
        const int c = (idx & 7) * 8;
        const size_t g = (size_t)(n0 + r) * FIN + kc + c;
        __pipeline_memcpy_async(sm + SB_ + r * LDS_ + c, wh + g, 16);
    }
}

__global__ __launch_bounds__(256)
void gemm_qk_wmma(const __half* __restrict__ xh,
                  const __half* __restrict__ wh,
                  __half* __restrict__ qout,
                  __half* __restrict__ kout)
{
    extern __shared__ __half sm[];
    const int tid = threadIdx.x;
    const int wid = tid >> 5;
    const int lane = tid & 31;
    const int warp_m = wid >> 1;          // 0..3
    const int warp_n = wid & 1;           // 0..1
    const int m0  = blockIdx.y * BM;
    const int n0  = blockIdx.x * BN;
    const bool is_q = (n0 < FQK);
    const float scale = is_q ? SCALING : 1.0f;

    wmma::fragment<wmma::accumulator, 16, 16, 16, float> acc[2][4];
#pragma unroll
    for (int mi = 0; mi < 2; ++mi)
#pragma unroll
        for (int f = 0; f < 4; ++f) wmma::fill_fragment(acc[mi][f], 0.0f);

    load_stage(sm, xh, wh, m0, n0, 0, tid);
    __pipeline_commit();
    load_stage(sm + STAGE_ELEMS, xh, wh, m0, n0, KC, tid);
    __pipeline_commit();

    const int nChunks = FIN / KC;   // 4
    for (int c = 0; c < nChunks; ++c) {
        __pipeline_wait_prior(1);
        __syncthreads();
        __half* st = sm + (c & 1) * STAGE_ELEMS;

#pragma unroll
        for (int ks = 0; ks < KC / 16; ++ks) {
            wmma::fragment<wmma::matrix_a, 16, 16, 16, __half, wmma::row_major> ah[2];
#pragma unroll
            for (int mi = 0; mi < 2; ++mi) {
                const int row = warp_m * 32 + mi * 16;
                wmma::load_matrix_sync(ah[mi], st + SA_ + row * LDS_ + ks * 16, LDS_);
            }
#pragma unroll
            for (int nf = 0; nf < 4; ++nf) {
                const int col = warp_n * 64 + nf * 16;
                wmma::fragment<wmma::matrix_b, 16, 16, 16, __half, wmma::col_major> bh;
                wmma::load_matrix_sync(bh, st + SB_ + col * LDS_ + ks * 16, LDS_);
#pragma unroll
                for (int mi = 0; mi < 2; ++mi)
                    wmma::mma_sync(acc[mi][nf], ah[mi], bh, acc[mi][nf]);
            }
        }
        __syncthreads();
        if (c + 2 < nChunks) {
            load_stage(st, xh, wh, m0, n0, (c + 2) * KC, tid);
        }
        __pipeline_commit();
    }

    // ---- epilogue: fp32 acc -> fp16 via per-warp smem scratch ----
    __syncthreads();   // all MMA reads of stage smem done; reuse as scratch
    float* buf = (float*)sm + wid * (16 * 64);   // 4 KB per warp
    __half* outp = is_q ? qout : kout;
    const int col0 = (is_q ? n0 : n0 - FQK) + warp_n * 64;

#pragma unroll
    for (int mi = 0; mi < 2; ++mi) {
        const int row0 = m0 + warp_m * 32 + mi * 16;
#pragma unroll
        for (int nf = 0; nf < 4; ++nf) {
#pragma unroll
            for (int t = 0; t < acc[mi][nf].num_elements; ++t)
                acc[mi][nf].x[t] *= scale;
            wmma::store_matrix_sync(buf + nf * 16, acc[mi][nf], 64, wmma::mem_row_major);
        }
        __syncwarp();
#pragma unroll
        for (int r = 0; r < 16; ++r) {
            float a = buf[r * 64 + 2 * lane];
            float b = buf[r * 64 + 2 * lane + 1];
            ((__half2*)(outp + (size_t)(row0 + r) * FQK + col0))[lane] =
                __halves2half2(__float2half(a), __float2half(b));
        }
        __syncwarp();
    }
}

// ===========================================================================
// Kernel 2: fused edge pass. One warp per src node; 8 lanes per edge,
// 4 edges per iteration. fp16 dot via HFMA2 (4 independent accumulators),
// fp32 cross-lane reduce (3 shfls). Pipelined k gather.
// ===========================================================================
#define SMEM_DEG 128

__device__ __forceinline__ int lower_bound_i(const int* __restrict__ a,
                                             int n, int v)
{
    int lo = 0, hi = n;
    while (lo < hi) {
        int mid = (lo + hi) >> 1;
        if (a[mid] < v) lo = mid + 1; else hi = mid;
    }
    return lo;
}

// dot of 4 uint4 (32 halves) q x k per lane; 4 indep half2 accumulators
__device__ __forceinline__ float dot_h8(const uint4* q, const uint4* k)
{
    const __half2* qh = (const __half2*)q;
    const __half2* kh2 = (const __half2*)k;
    __half2 a0 = __hmul2(qh[0], kh2[0]);
    __half2 a1 = __hmul2(qh[1], kh2[1]);
    __half2 a2 = __hmul2(qh[2], kh2[2]);
    __half2 a3 = __hmul2(qh[3], kh2[3]);
#pragma unroll
    for (int i = 1; i < 4; ++i) {
        a0 = __hfma2(qh[4 * i + 0], kh2[4 * i + 0], a0);
        a1 = __hfma2(qh[4 * i + 1], kh2[4 * i + 1], a1);
        a2 = __hfma2(qh[4 * i + 2], kh2[4 * i + 2], a2);
        a3 = __hfma2(qh[4 * i + 3], kh2[4 * i + 3], a3);
    }
    float2 f0 = __half22float2(a0);
    float2 f1 = __half22float2(a1);
    float2 f2 = __half22float2(a2);
    float2 f3 = __half22float2(a3);
    return ((f0.x + f0.y) + (f1.x + f1.y)) + ((f2.x + f2.y) + (f3.x + f3.y));
}

__global__ __launch_bounds__(256)
void edge_fused_kernel(const int* __restrict__ ei,
                       const __half* __restrict__ qh,
                       const __half* __restrict__ kh,
                       float* __restrict__ out,
                       int E, int N)
{
    __shared__ float exbuf[8][SMEM_DEG];

    const int wslot = threadIdx.x >> 5;
    const int node  = (blockIdx.x * blockDim.x + threadIdx.x) >> 5;
    const int lane  = threadIdx.x & 31;
    const int g     = lane >> 3;          // edge slot 0..3
    const int u     = lane & 7;           // k-chunk owner within 8-lane group
    if (node >= N) return;

    const int lo = lower_bound_i(ei, E, node);
    const int hi = lower_bound_i(ei, E, node + 1);
    const int deg = hi - lo;
    if (deg <= 0) return;

    // lane u owns uint4s {u, u+8, u+16, u+24} of the 32-uint4 row
    const uint4* qp = (const uint4*)(qh + (size_t)node * FQK);
    uint4 qr[4];
#pragma unroll
    for (int i = 0; i < 4; ++i) qr[i] = qp[u + 8 * i];

    const int* __restrict__ dest = ei + E;
    const int nIter = (deg + 3) >> 2;
    float sum = 0.0f;

    if (deg <= SMEM_DEG) {
        // prime the pipeline
        int j = lo + g;
        int jj = (j < hi) ? j : (hi - 1);
        const uint4* kp = (const uint4*)(kh + (size_t)dest[jj] * FQK);
        uint4 kr[4];
#pragma unroll
        for (int i = 0; i < 4; ++i) kr[i] = kp[u + 8 * i];

        for (int it = 0; it < nIter; ++it) {
            uint4 cr[4];
#pragma unroll
            for (int i = 0; i < 4; ++i) cr[i] = kr[i];
            const int jn = j + 4;
            if (jn < hi) {
                const uint4* kn = (const uint4*)(kh + (size_t)dest[jn] * FQK);
#pragma unroll
                for (int i = 0; i < 4; ++i) kr[i] = kn[u + 8 * i];
            }
            float p = dot_h8(qr, cr);
#pragma unroll
            for (int o = 1; o < 8; o <<= 1)
                p += __shfl_xor_sync(0xffffffffu, p, o);

            float ex = __expf(p);
            if (j < hi) {
                sum += ex;
                if (u == 0) exbuf[wslot][j - lo] = ex;
            }
            j = jn;
        }
        // combine the four group sums
        sum += __shfl_xor_sync(0xffffffffu, sum, 8);
        sum += __shfl_xor_sync(0xffffffffu, sum, 16);
        const float inv = 1.0f / sum;
        __syncwarp();
        for (int i = lane; i < deg; i += 32)
            out[lo + i] = exbuf[wslot][i] * inv;
    } else {
        // fallback for very high degree: stage in gmem, two passes
        for (int it = 0; it < nIter; ++it) {
            const int j = lo + 4 * it + g;
            const int jj = (j < hi) ? j : (hi - 1);
            const uint4* kp = (const uint4*)(kh + (size_t)dest[jj] * FQK);
            uint4 cr[4];
#pragma unroll
            for (int i = 0; i < 4; ++i) cr[i] = kp[u + 8 * i];
            float p = dot_h8(qr, cr);
#pragma unroll
            for (int o = 1; o < 8; o <<= 1)
                p += __shfl_xor_sync(0xffffffffu, p, o);
            float ex = __expf(p);
            if (j < hi) {
                sum += ex;
                if (u == 0) out[j] = ex;
            }
        }
        sum += __shfl_xor_sync(0xffffffffu, sum, 8);
        sum += __shfl_xor_sync(0xffffffffu, sum, 16);
        const float inv = 1.0f / sum;
        __threadfence_block();
        __syncwarp();
        for (int i = lane; i < deg; i += 32)
            out[lo + i] *= inv;
    }
}

// ===========================================================================
extern "C" void kernel_launch(void* const* d_in, const int* in_sizes, int n_in,
                              void* d_out, int out_size)
{
    const float* x   = (const float*)d_in[0];
    const int*   ei  = (const int*)d_in[1];
    const float* W   = (const float*)d_in[2];
    float*       out = (float*)d_out;

    const int N = in_sizes[0] / FIN;     // 20000
    const int E = in_sizes[1] / 2;       // 640000

    __half* qht; cudaGetSymbolAddress((void**)&qht, g_qh);
    __half* kht; cudaGetSymbolAddress((void**)&kht, g_kh);
    __half* xh;  cudaGetSymbolAddress((void**)&xh,  g_xh);
    __half* wh;  cudaGetSymbolAddress((void**)&wh,  g_wh);

    // 0) convert x, W -> fp16
    {
        int n4x = N * FIN / 4;
        convert_kernel<<<(n4x + 255) / 256, 256>>>(x, xh, n4x);
        int n4w = NQK * FIN / 4;
        convert_kernel<<<(n4w + 255) / 256, 256>>>(W, wh, n4w);
    }
    // 1) projection GEMM (fp16 WMMA, cp.async double-buffered)
    {
        cudaFuncSetAttribute(gemm_qk_wmma,
                             cudaFuncAttributeMaxDynamicSharedMemorySize,
                             SM_BYTES);
        dim3 grid(NQK / BN, MROWS / BM);
        gemm_qk_wmma<<<grid, 256, SM_BYTES>>>(xh, wh, qht, kht);
    }
    // 2) fused edge dot + scatter softmax (one warp per node)
    {
        int blocks = (N * 32 + 255) / 256;
        edge_fused_kernel<<<blocks, 256>>>(ei, qht, kht, out, E, N);
    }
}